// round 11
// baseline (speedup 1.0000x reference)
#include <cuda_runtime.h>
#include <cuda_fp16.h>
#include <mma.h>
#include <cstdint>

#define EMBED 1024
#define NHEADS 16
#define HDIM 64
#define BATCH 2
#define SEQ 2048
#define MTOT 4096

// fp16 scratch (device globals -- no runtime allocation allowed)
__device__ __half g_hXq[MTOT * EMBED];
__device__ __half g_hXk[MTOT * EMBED];
__device__ __half g_hXv[MTOT * EMBED];
__device__ __half g_hWq[EMBED * EMBED];
__device__ __half g_hWk[EMBED * EMBED];
__device__ __half g_hWv[EMBED * EMBED];
__device__ __half g_hWo[EMBED * EMBED];
__device__ __half g_hQ[MTOT * EMBED];
__device__ __half g_hK[MTOT * EMBED];
__device__ __half g_hV[MTOT * EMBED];
__device__ __half g_hCTX[MTOT * EMBED];

__device__ __forceinline__ void cp16(uint32_t dst, const void* src) {
    asm volatile("cp.async.cg.shared.global [%0], [%1], 16;\n"
                 :: "r"(dst), "l"(src));
}
#define CP_COMMIT() asm volatile("cp.async.commit_group;\n")
#define CP_WAIT(n)  asm volatile("cp.async.wait_group %0;\n" :: "n"(n))

__device__ __forceinline__ unsigned pack_h2(float a, float b) {
    __half2 h = __floats2half2_rn(a, b);
    return *(unsigned*)&h;
}

__device__ __forceinline__ float ex2(float x) {
    float r;
    asm("ex2.approx.f32 %0, %1;" : "=f"(r) : "f"(x));
    return r;
}

// ---- raw mma helpers (fragment layouts validated in attention kernel) ----
__device__ __forceinline__ void ldsm_x4(uint32_t* r, uint32_t addr) {
    asm volatile("ldmatrix.sync.aligned.m8n8.x4.shared.b16 {%0,%1,%2,%3}, [%4];"
        : "=r"(r[0]), "=r"(r[1]), "=r"(r[2]), "=r"(r[3]) : "r"(addr));
}
__device__ __forceinline__ void ldsm_x4_t(uint32_t* r, uint32_t addr) {
    asm volatile("ldmatrix.sync.aligned.m8n8.x4.trans.shared.b16 {%0,%1,%2,%3}, [%4];"
        : "=r"(r[0]), "=r"(r[1]), "=r"(r[2]), "=r"(r[3]) : "r"(addr));
}
__device__ __forceinline__ void mma16816(float* c, const uint32_t* a,
                                         uint32_t b0, uint32_t b1) {
    asm volatile(
        "mma.sync.aligned.m16n8k16.row.col.f32.f16.f16.f32 "
        "{%0,%1,%2,%3}, {%4,%5,%6,%7}, {%8,%9}, {%0,%1,%2,%3};"
        : "+f"(c[0]), "+f"(c[1]), "+f"(c[2]), "+f"(c[3])
        : "r"(a[0]), "r"(a[1]), "r"(a[2]), "r"(a[3]), "r"(b0), "r"(b1));
}

#define ALD 72   // shared leading dim (halfs) for all 64/128-wide k tiles
// ldmatrix x4 lane address within a [rows x ALD] half tile
__device__ __forceinline__ uint32_t ldsm_addr(uint32_t base, int row0, int col0,
                                              int lane) {
    int g = lane >> 3, l = lane & 7;
    int r = row0 + ((g & 1) << 3) + l;
    int c = col0 + ((g >> 1) << 3);
    return base + (uint32_t)(r * ALD + c) * 2;
}

// ---------------------------------------------------------------------------
// fp32 -> fp16 conversion of inputs + weights (2 float4 per thread)
// ---------------------------------------------------------------------------
#define X4 1048576
#define W4 262144

__global__ void cvt_all(
    const float* __restrict__ xq, const float* __restrict__ xk,
    const float* __restrict__ xv,
    const float* __restrict__ wq, const float* __restrict__ wk,
    const float* __restrict__ wv, const float* __restrict__ wo,
    __half* hxq, __half* hxk, __half* hxv,
    __half* hwq, __half* hwk, __half* hwv, __half* hwo)
{
    int i0 = (blockIdx.x * blockDim.x + threadIdx.x) * 2;
    const float* src; __half* dst; int off;
    if      (i0 < X4)            { src = xq; dst = hxq; off = i0; }
    else if (i0 < 2 * X4)        { src = xk; dst = hxk; off = i0 - X4; }
    else if (i0 < 3 * X4)        { src = xv; dst = hxv; off = i0 - 2 * X4; }
    else if (i0 < 3 * X4 + W4)   { src = wq; dst = hwq; off = i0 - 3 * X4; }
    else if (i0 < 3 * X4 + 2*W4) { src = wk; dst = hwk; off = i0 - 3*X4 - W4; }
    else if (i0 < 3 * X4 + 3*W4) { src = wv; dst = hwv; off = i0 - 3*X4 - 2*W4; }
    else                         { src = wo; dst = hwo; off = i0 - 3*X4 - 3*W4; }
#pragma unroll
    for (int t = 0; t < 2; t++) {
        float4 v = ((const float4*)src)[off + t];
        uint2 u;
        u.x = pack_h2(v.x, v.y); u.y = pack_h2(v.z, v.w);
        ((uint2*)dst)[off + t] = u;
    }
}

// ---------------------------------------------------------------------------
// GEMM v2 (raw mma): 128x128 block tile, 4 warps (2m x 2n) of 64x64,
// K-tile 64, 2-stage cp.async, accumulators stored straight to global.
// ---------------------------------------------------------------------------
#define GTILE (128 * ALD)                 // halfs per operand tile
#define GSTAGE (2 * GTILE)                // A+B per stage (halfs)
#define GEMM_SMEM (2 * GSTAGE * 2)        // 73728 B

__device__ __forceinline__ void gemm_fill(
    const __half* __restrict__ A, const __half* __restrict__ W,
    int m0, int n0, uint32_t sb, int s, int kt, int tid)
{
    int so = s * GSTAGE;
#pragma unroll
    for (int i = 0; i < 8; i++) {
        int idx = tid + i * 128;          // 0..1023
        int row = idx >> 3;               // 0..127
        int c8  = (idx & 7) * 8;          // 0..56
        cp16(sb + (uint32_t)(so + row * ALD + c8) * 2,
             &A[(size_t)(m0 + row) * 1024 + kt + c8]);
        cp16(sb + (uint32_t)(so + GTILE + row * ALD + c8) * 2,
             &W[(size_t)(n0 + row) * 1024 + kt + c8]);
    }
    CP_COMMIT();
}

// acc[mi][n8][4]: mi = m16 tile (0..3), n8 = n8 tile (0..7)
__device__ __forceinline__ void gemm_mainloop_raw(
    const __half* __restrict__ A, const __half* __restrict__ W,
    int m0, int n0, uint32_t sb, float acc[4][8][4])
{
    const int tid  = threadIdx.x;
    const int warp = tid >> 5;
    const int lane = tid & 31;
    const int wm   = warp >> 1;          // 0..1 -> rows wm*64
    const int wn   = warp & 1;           // 0..1 -> cols wn*64

    gemm_fill(A, W, m0, n0, sb, 0, 0, tid);
    gemm_fill(A, W, m0, n0, sb, 1, 64, tid);

    for (int t = 0; t < 16; t++) {
        if (t < 15) { CP_WAIT(1); } else { CP_WAIT(0); }
        __syncthreads();
        const uint32_t As = sb + (uint32_t)((t & 1) * GSTAGE) * 2;
        const uint32_t Bs = As + (uint32_t)GTILE * 2;

#pragma unroll
        for (int kk = 0; kk < 4; kk++) {
            uint32_t a[4][4];
#pragma unroll
            for (int mi = 0; mi < 4; mi++)
                ldsm_x4(a[mi], ldsm_addr(As, wm * 64 + mi * 16, kk * 16, lane));
#pragma unroll
            for (int nj = 0; nj < 4; nj++) {
                uint32_t bf[4];
                ldsm_x4(bf, ldsm_addr(Bs, wn * 64 + nj * 16, kk * 16, lane));
#pragma unroll
                for (int mi = 0; mi < 4; mi++) {
                    mma16816(acc[mi][2 * nj],     a[mi], bf[0], bf[2]);
                    mma16816(acc[mi][2 * nj + 1], a[mi], bf[1], bf[3]);
                }
            }
        }
        __syncthreads();
        if (t + 2 <= 15)
            gemm_fill(A, W, m0, n0, sb, t & 1, (t + 2) * 64, tid);
    }
}

// Projections: half in, half out (Q pre-scaled by 0.125*log2e)
__global__ __launch_bounds__(128, 3) void proj3_kernel(
    const __half* __restrict__ xq, const __half* __restrict__ xk,
    const __half* __restrict__ xv,
    const __half* __restrict__ wq, const __half* __restrict__ wk,
    const __half* __restrict__ wv,
    __half* q, __half* k, __half* v)
{
    extern __shared__ __half gsm[];
    const __half* A; const __half* W; __half* C; float scale;
    if (blockIdx.z == 0)      { A = xq; W = wq; C = q; scale = 0.125f * 1.44269504f; }
    else if (blockIdx.z == 1) { A = xk; W = wk; C = k; scale = 1.0f; }
    else                      { A = xv; W = wv; C = v; scale = 1.0f; }
    const int m0 = blockIdx.y * 128, n0 = blockIdx.x * 128;
    const int warp = threadIdx.x >> 5, lane = threadIdx.x & 31;
    const int wm = warp >> 1, wn = warp & 1;
    const int qr = lane >> 2, qc = lane & 3;
    uint32_t sb = (uint32_t)__cvta_generic_to_shared(gsm);

    float acc[4][8][4];
#pragma unroll
    for (int mi = 0; mi < 4; mi++)
#pragma unroll
        for (int nj = 0; nj < 8; nj++)
#pragma unroll
            for (int e = 0; e < 4; e++) acc[mi][nj][e] = 0.0f;

    gemm_mainloop_raw(A, W, m0, n0, sb, acc);

    // direct global epilogue: u32 fp16-pair stores
#pragma unroll
    for (int mi = 0; mi < 4; mi++) {
        const size_t r0 = (size_t)(m0 + wm * 64 + mi * 16 + qr) * 1024;
#pragma unroll
        for (int nj = 0; nj < 8; nj++) {
            int col = n0 + wn * 64 + nj * 8 + qc * 2;
            *(unsigned*)&C[r0 + col] =
                pack_h2(acc[mi][nj][0] * scale, acc[mi][nj][1] * scale);
            *(unsigned*)&C[r0 + 8 * 1024 + col] =
                pack_h2(acc[mi][nj][2] * scale, acc[mi][nj][3] * scale);
        }
    }
}

// Output projection: half in, fp32 out + bias (direct float2 stores)
__global__ __launch_bounds__(128, 3) void gemm_bias_kernel(
    const __half* __restrict__ A, const __half* __restrict__ W,
    float* __restrict__ C, const float* __restrict__ bias)
{
    extern __shared__ __half gsm[];
    const int m0 = blockIdx.y * 128, n0 = blockIdx.x * 128;
    const int warp = threadIdx.x >> 5, lane = threadIdx.x & 31;
    const int wm = warp >> 1, wn = warp & 1;
    const int qr = lane >> 2, qc = lane & 3;
    uint32_t sb = (uint32_t)__cvta_generic_to_shared(gsm);

    float acc[4][8][4];
#pragma unroll
    for (int mi = 0; mi < 4; mi++)
#pragma unroll
        for (int nj = 0; nj < 8; nj++)
#pragma unroll
            for (int e = 0; e < 4; e++) acc[mi][nj][e] = 0.0f;

    gemm_mainloop_raw(A, W, m0, n0, sb, acc);

#pragma unroll
    for (int mi = 0; mi < 4; mi++) {
        const size_t r0 = (size_t)(m0 + wm * 64 + mi * 16 + qr) * 1024;
#pragma unroll
        for (int nj = 0; nj < 8; nj++) {
            int col = n0 + wn * 64 + nj * 8 + qc * 2;
            float b0 = __ldg(&bias[col]), b1 = __ldg(&bias[col + 1]);
            float2 v0 = { acc[mi][nj][0] + b0, acc[mi][nj][1] + b1 };
            float2 v1 = { acc[mi][nj][2] + b0, acc[mi][nj][3] + b1 };
            *(float2*)&C[r0 + col] = v0;
            *(float2*)&C[r0 + 8 * 1024 + col] = v1;
        }
    }
}

// ---------------------------------------------------------------------------
// Flash attention v5 (unchanged from R10): raw mma, register P, chunked
// softmax, Q overlay, 3 CTAs/SM.
// ---------------------------------------------------------------------------
#define AST 36864
#define AOFF_V 18432
#define AOFF_QTMP 36864
#define AOFF_LR  73728
#define ATTN_SMEM 74240

__global__ __launch_bounds__(256, 3) void attn_kernel(
    const __half* __restrict__ Q, const __half* __restrict__ K,
    const __half* __restrict__ V, __half* __restrict__ CTX)
{
    extern __shared__ char smraw[];
    float* l_red = (float*)(smraw + AOFF_LR);
    uint32_t sb = (uint32_t)__cvta_generic_to_shared(smraw);

    const int tid  = threadIdx.x;
    const int warp = tid >> 5;
    const int lane = tid & 31;
    const int wm   = warp >> 1;
    const int wk2  = warp & 1;
    const int qr   = lane >> 2;
    const int qc   = lane & 3;
    const int b    = blockIdx.y >> 4;
    const int h    = blockIdx.y & 15;
    const int s0   = blockIdx.x * 64;
    const size_t base = (size_t)b * SEQ * EMBED + (size_t)h * HDIM;

#pragma unroll
    for (int i = 0; i < 2; i++) {
        int idx = tid + i * 256;
        int row = idx >> 3;
        int c8  = (idx & 7) * 8;
        cp16(sb + AOFF_QTMP + (row * ALD + c8) * 2,
             &Q[base + (size_t)(s0 + row) * 1024 + c8]);
    }
#pragma unroll
    for (int i = 0; i < 4; i++) {
        int idx = tid + i * 256;
        int row = idx >> 3;
        int c8  = (idx & 7) * 8;
        cp16(sb + (row * ALD + c8) * 2,
             &K[base + (size_t)row * 1024 + c8]);
        cp16(sb + AOFF_V + (row * ALD + c8) * 2,
             &V[base + (size_t)row * 1024 + c8]);
    }
    CP_COMMIT();
    if (tid < 64) l_red[tid] = 0.0f;

    CP_WAIT(0);
    __syncthreads();

    uint32_t qf[4][4];
#pragma unroll
    for (int kd = 0; kd < 4; kd++)
        ldsm_x4(qf[kd], ldsm_addr(sb + AOFF_QTMP, wm * 16, kd * 16, lane));
    __syncthreads();

    float oacc[8][4];
#pragma unroll
    for (int i = 0; i < 8; i++)
#pragma unroll
        for (int e = 0; e < 4; e++) oacc[i][e] = 0.0f;
    float lsum0 = 0.0f, lsum1 = 0.0f;

    for (int j = 0; j < 16; j++) {
        if (j > 0) { CP_WAIT(0); __syncthreads(); }
        if (j < 15) {
            uint32_t st = ((j + 1) & 1) ? AST : 0u;
            const size_t gb = base + (size_t)((j + 1) * 128) * 1024;
#pragma unroll
            for (int i = 0; i < 4; i++) {
                int idx = tid + i * 256;
                int row = idx >> 3;
                int c8  = (idx & 7) * 8;
                cp16(sb + st + (row * ALD + c8) * 2,
                     &K[gb + (size_t)row * 1024 + c8]);
                cp16(sb + st + AOFF_V + (row * ALD + c8) * 2,
                     &V[gb + (size_t)row * 1024 + c8]);
            }
            CP_COMMIT();
        }

        const uint32_t bK = sb + ((j & 1) ? AST : 0u);
        const uint32_t bV = bK + AOFF_V;

#pragma unroll
        for (int h2 = 0; h2 < 2; h2++) {
            const int key0 = wk2 * 64 + h2 * 32;

            float sc[4][4];
#pragma unroll
            for (int i = 0; i < 4; i++)
#pragma unroll
                for (int e = 0; e < 4; e++) sc[i][e] = 0.0f;
#pragma unroll
            for (int kd = 0; kd < 4; kd++) {
#pragma unroll
                for (int kn = 0; kn < 2; kn++) {
                    uint32_t bf[4];
                    ldsm_x4(bf, ldsm_addr(bK, key0 + kn * 16, kd * 16, lane));
                    mma16816(sc[2 * kn],     qf[kd], bf[0], bf[2]);
                    mma16816(sc[2 * kn + 1], qf[kd], bf[1], bf[3]);
                }
            }

            uint32_t pf[2][4];
#pragma unroll
            for (int t = 0; t < 2; t++) {
                float e00 = ex2(sc[2*t][0]),   e01 = ex2(sc[2*t][1]);
                float e02 = ex2(sc[2*t][2]),   e03 = ex2(sc[2*t][3]);
                float e10 = ex2(sc[2*t+1][0]), e11 = ex2(sc[2*t+1][1]);
                float e12 = ex2(sc[2*t+1][2]), e13 = ex2(sc[2*t+1][3]);
                lsum0 += e00 + e01 + e10 + e11;
                lsum1 += e02 + e03 + e12 + e13;
                pf[t][0] = pack_h2(e00, e01);
                pf[t][1] = pack_h2(e02, e03);
                pf[t][2] = pack_h2(e10, e11);
                pf[t][3] = pack_h2(e12, e13);
            }

#pragma unroll
            for (int t = 0; t < 2; t++) {
#pragma unroll
                for (int dn = 0; dn < 4; dn++) {
                    uint32_t vf[4];
                    ldsm_x4_t(vf, ldsm_addr(bV, key0 + t * 16, dn * 16, lane));
                    mma16816(oacc[2 * dn],     pf[t], vf[0], vf[1]);
                    mma16816(oacc[2 * dn + 1], pf[t], vf[2], vf[3]);
                }
            }
        }
    }

    lsum0 += __shfl_xor_sync(0xffffffffu, lsum0, 1);
    lsum0 += __shfl_xor_sync(0xffffffffu, lsum0, 2);
    lsum1 += __shfl_xor_sync(0xffffffffu, lsum1, 1);
    lsum1 += __shfl_xor_sync(0xffffffffu, lsum1, 2);
    if (qc == 0) {
        atomicAdd(&l_red[wm * 16 + qr], lsum0);
        atomicAdd(&l_red[wm * 16 + qr + 8], lsum1);
    }
    __syncthreads();

    float* Cs = (float*)smraw;
    if (wk2 == 0) {
#pragma unroll
        for (int dn = 0; dn < 8; dn++) {
            int col = dn * 8 + qc * 2;
            Cs[(wm * 16 + qr) * 68 + col]         = oacc[dn][0];
            Cs[(wm * 16 + qr) * 68 + col + 1]     = oacc[dn][1];
            Cs[(wm * 16 + qr + 8) * 68 + col]     = oacc[dn][2];
            Cs[(wm * 16 + qr + 8) * 68 + col + 1] = oacc[dn][3];
        }
    }
    __syncthreads();
    if (wk2 == 1) {
#pragma unroll
        for (int dn = 0; dn < 8; dn++) {
            int col = dn * 8 + qc * 2;
            Cs[(wm * 16 + qr) * 68 + col]         += oacc[dn][0];
            Cs[(wm * 16 + qr) * 68 + col + 1]     += oacc[dn][1];
            Cs[(wm * 16 + qr + 8) * 68 + col]     += oacc[dn][2];
            Cs[(wm * 16 + qr + 8) * 68 + col + 1] += oacc[dn][3];
        }
    }
    __syncthreads();

#pragma unroll
    for (int i = 0; i < 2; i++) {
        int idx = tid + i * 256;
        int row = idx >> 3;
        int c8  = (idx & 7) * 8;
        float rl = __frcp_rn(l_red[row]);
        float4 v0 = *(float4*)&Cs[row * 68 + c8];
        float4 v1 = *(float4*)&Cs[row * 68 + c8 + 4];
        uint4 u;
        u.x = pack_h2(v0.x * rl, v0.y * rl);
        u.y = pack_h2(v0.z * rl, v0.w * rl);
        u.z = pack_h2(v1.x * rl, v1.y * rl);
        u.w = pack_h2(v1.z * rl, v1.w * rl);
        *(uint4*)&CTX[base + (size_t)(s0 + row) * 1024 + c8] = u;
    }
}

// ---------------------------------------------------------------------------
// Launch
// ---------------------------------------------------------------------------
extern "C" void kernel_launch(void* const* d_in, const int* in_sizes, int n_in,
                              void* d_out, int out_size)
{
    const float* key   = (const float*)d_in[0];
    const float* query = (const float*)d_in[1];
    const float* value = (const float*)d_in[2];
    const float* Wq    = (const float*)d_in[3];
    const float* Wk    = (const float*)d_in[4];
    const float* Wv    = (const float*)d_in[5];
    const float* Wo    = (const float*)d_in[6];
    const float* bo    = (const float*)d_in[7];
    float* out = (float*)d_out;

    __half *hXq, *hXk, *hXv, *hWq, *hWk, *hWv, *hWo, *hQ, *hK, *hV, *hCTX;
    cudaGetSymbolAddress((void**)&hXq, g_hXq);
    cudaGetSymbolAddress((void**)&hXk, g_hXk);
    cudaGetSymbolAddress((void**)&hXv, g_hXv);
    cudaGetSymbolAddress((void**)&hWq, g_hWq);
    cudaGetSymbolAddress((void**)&hWk, g_hWk);
    cudaGetSymbolAddress((void**)&hWv, g_hWv);
    cudaGetSymbolAddress((void**)&hWo, g_hWo);
    cudaGetSymbolAddress((void**)&hQ, g_hQ);
    cudaGetSymbolAddress((void**)&hK, g_hK);
    cudaGetSymbolAddress((void**)&hV, g_hV);
    cudaGetSymbolAddress((void**)&hCTX, g_hCTX);

    const int cvt_total = 3 * X4 + 4 * W4;
    cvt_all<<<cvt_total / 512, 256>>>(query, key, value, Wq, Wk, Wv, Wo,
                                      hXq, hXk, hXv, hWq, hWk, hWv, hWo);

    cudaFuncSetAttribute(proj3_kernel,
        cudaFuncAttributeMaxDynamicSharedMemorySize, GEMM_SMEM);
    cudaFuncSetAttribute(gemm_bias_kernel,
        cudaFuncAttributeMaxDynamicSharedMemorySize, GEMM_SMEM);
    cudaFuncSetAttribute(attn_kernel,
        cudaFuncAttributeMaxDynamicSharedMemorySize, ATTN_SMEM);

    dim3 proj_grid(EMBED / 128, MTOT / 128, 3);
    proj3_kernel<<<proj_grid, 128, GEMM_SMEM>>>(
        hXq, hXk, hXv, hWq, hWk, hWv, hQ, hK, hV);

    attn_kernel<<<dim3(SEQ / 64, BATCH * NHEADS), 256, ATTN_SMEM>>>(
        hQ, hK, hV, hCTX);

    gemm_bias_kernel<<<dim3(EMBED / 128, MTOT / 128), 128, GEMM_SMEM>>>(
        hCTX, hWo, out, bo);
}

// round 12
// speedup vs baseline: 1.0143x; 1.0143x over previous
#include <cuda_runtime.h>
#include <cuda_fp16.h>
#include <mma.h>
#include <cstdint>

#define EMBED 1024
#define NHEADS 16
#define HDIM 64
#define BATCH 2
#define SEQ 2048
#define MTOT 4096

// fp16 scratch (device globals -- no runtime allocation allowed)
__device__ __half g_hXq[MTOT * EMBED];
__device__ __half g_hXk[MTOT * EMBED];
__device__ __half g_hXv[MTOT * EMBED];
__device__ __half g_hWq[EMBED * EMBED];
__device__ __half g_hWk[EMBED * EMBED];
__device__ __half g_hWv[EMBED * EMBED];
__device__ __half g_hWo[EMBED * EMBED];
__device__ __half g_hQ[MTOT * EMBED];
__device__ __half g_hK[MTOT * EMBED];
__device__ __half g_hV[MTOT * EMBED];
__device__ __half g_hCTX[MTOT * EMBED];

__device__ __forceinline__ void cp16(uint32_t dst, const void* src) {
    asm volatile("cp.async.cg.shared.global [%0], [%1], 16;\n"
                 :: "r"(dst), "l"(src));
}
#define CP_COMMIT() asm volatile("cp.async.commit_group;\n")
#define CP_WAIT(n)  asm volatile("cp.async.wait_group %0;\n" :: "n"(n))

__device__ __forceinline__ unsigned pack_h2(float a, float b) {
    __half2 h = __floats2half2_rn(a, b);
    return *(unsigned*)&h;
}

__device__ __forceinline__ float ex2(float x) {
    float r;
    asm("ex2.approx.f32 %0, %1;" : "=f"(r) : "f"(x));
    return r;
}

// ---- raw mma helpers ----
__device__ __forceinline__ void ldsm_x4(uint32_t* r, uint32_t addr) {
    asm volatile("ldmatrix.sync.aligned.m8n8.x4.shared.b16 {%0,%1,%2,%3}, [%4];"
        : "=r"(r[0]), "=r"(r[1]), "=r"(r[2]), "=r"(r[3]) : "r"(addr));
}
__device__ __forceinline__ void ldsm_x4_t(uint32_t* r, uint32_t addr) {
    asm volatile("ldmatrix.sync.aligned.m8n8.x4.trans.shared.b16 {%0,%1,%2,%3}, [%4];"
        : "=r"(r[0]), "=r"(r[1]), "=r"(r[2]), "=r"(r[3]) : "r"(addr));
}
__device__ __forceinline__ void mma16816(float* c, const uint32_t* a,
                                         uint32_t b0, uint32_t b1) {
    asm volatile(
        "mma.sync.aligned.m16n8k16.row.col.f32.f16.f16.f32 "
        "{%0,%1,%2,%3}, {%4,%5,%6,%7}, {%8,%9}, {%0,%1,%2,%3};"
        : "+f"(c[0]), "+f"(c[1]), "+f"(c[2]), "+f"(c[3])
        : "r"(a[0]), "r"(a[1]), "r"(a[2]), "r"(a[3]), "r"(b0), "r"(b1));
}

#define ALD 72
__device__ __forceinline__ uint32_t ldsm_addr(uint32_t base, int row0, int col0,
                                              int lane) {
    int g = lane >> 3, l = lane & 7;
    int r = row0 + ((g & 1) << 3) + l;
    int c = col0 + ((g >> 1) << 3);
    return base + (uint32_t)(r * ALD + c) * 2;
}

// ---------------------------------------------------------------------------
// fp32 -> fp16 conversion of inputs + weights (2 float4 per thread)
// ---------------------------------------------------------------------------
#define X4 1048576
#define W4 262144

__global__ void cvt_all(
    const float* __restrict__ xq, const float* __restrict__ xk,
    const float* __restrict__ xv,
    const float* __restrict__ wq, const float* __restrict__ wk,
    const float* __restrict__ wv, const float* __restrict__ wo,
    __half* hxq, __half* hxk, __half* hxv,
    __half* hwq, __half* hwk, __half* hwv, __half* hwo)
{
    int i0 = (blockIdx.x * blockDim.x + threadIdx.x) * 2;
    const float* src; __half* dst; int off;
    if      (i0 < X4)            { src = xq; dst = hxq; off = i0; }
    else if (i0 < 2 * X4)        { src = xk; dst = hxk; off = i0 - X4; }
    else if (i0 < 3 * X4)        { src = xv; dst = hxv; off = i0 - 2 * X4; }
    else if (i0 < 3 * X4 + W4)   { src = wq; dst = hwq; off = i0 - 3 * X4; }
    else if (i0 < 3 * X4 + 2*W4) { src = wk; dst = hwk; off = i0 - 3*X4 - W4; }
    else if (i0 < 3 * X4 + 3*W4) { src = wv; dst = hwv; off = i0 - 3*X4 - 2*W4; }
    else                         { src = wo; dst = hwo; off = i0 - 3*X4 - 3*W4; }
#pragma unroll
    for (int t = 0; t < 2; t++) {
        float4 v = ((const float4*)src)[off + t];
        uint2 u;
        u.x = pack_h2(v.x, v.y); u.y = pack_h2(v.z, v.w);
        ((uint2*)dst)[off + t] = u;
    }
}

// ---------------------------------------------------------------------------
// GEMM v3 (raw mma): 128(M) x 64(N) block tile, 4 warps (2m x 2n) of 64x32.
// K-tile 64, 2-stage cp.async. Grid doubles vs v2 -> 4 CTAs/SM.
// ---------------------------------------------------------------------------
#define GT_A (128 * ALD)                  // A tile halfs
#define GT_B (64 * ALD)                   // B tile halfs
#define GSTAGE (GT_A + GT_B)              // halfs per stage
#define GEMM_SMEM (2 * GSTAGE * 2)        // 55296 B

__device__ __forceinline__ void gemm_fill(
    const __half* __restrict__ A, const __half* __restrict__ W,
    int m0, int n0, uint32_t sb, int s, int kt, int tid)
{
    int so = s * GSTAGE;
    // A: 128 rows x 64 halfs = 1024 cp16 -> 8 per thread
#pragma unroll
    for (int i = 0; i < 8; i++) {
        int idx = tid + i * 128;
        int row = idx >> 3;
        int c8  = (idx & 7) * 8;
        cp16(sb + (uint32_t)(so + row * ALD + c8) * 2,
             &A[(size_t)(m0 + row) * 1024 + kt + c8]);
    }
    // B: 64 rows -> 512 cp16 -> 4 per thread
#pragma unroll
    for (int i = 0; i < 4; i++) {
        int idx = tid + i * 128;
        int row = idx >> 3;
        int c8  = (idx & 7) * 8;
        cp16(sb + (uint32_t)(so + GT_A + row * ALD + c8) * 2,
             &W[(size_t)(n0 + row) * 1024 + kt + c8]);
    }
    CP_COMMIT();
}

// acc[mi][nj][4]: mi = m16 tile (0..3), nj = n8 tile (0..3)
__device__ __forceinline__ void gemm_mainloop_raw(
    const __half* __restrict__ A, const __half* __restrict__ W,
    int m0, int n0, uint32_t sb, float acc[4][4][4])
{
    const int tid  = threadIdx.x;
    const int warp = tid >> 5;
    const int lane = tid & 31;
    const int wm   = warp >> 1;          // 0..1 -> rows wm*64
    const int wn   = warp & 1;           // 0..1 -> cols wn*32

    gemm_fill(A, W, m0, n0, sb, 0, 0, tid);
    gemm_fill(A, W, m0, n0, sb, 1, 64, tid);

    for (int t = 0; t < 16; t++) {
        if (t < 15) { CP_WAIT(1); } else { CP_WAIT(0); }
        __syncthreads();
        const uint32_t As = sb + (uint32_t)((t & 1) * GSTAGE) * 2;
        const uint32_t Bs = As + (uint32_t)GT_A * 2;

#pragma unroll
        for (int kk = 0; kk < 4; kk++) {
            uint32_t a[4][4];
#pragma unroll
            for (int mi = 0; mi < 4; mi++)
                ldsm_x4(a[mi], ldsm_addr(As, wm * 64 + mi * 16, kk * 16, lane));
#pragma unroll
            for (int nj2 = 0; nj2 < 2; nj2++) {
                uint32_t bf[4];
                ldsm_x4(bf, ldsm_addr(Bs, wn * 32 + nj2 * 16, kk * 16, lane));
#pragma unroll
                for (int mi = 0; mi < 4; mi++) {
                    mma16816(acc[mi][2 * nj2],     a[mi], bf[0], bf[2]);
                    mma16816(acc[mi][2 * nj2 + 1], a[mi], bf[1], bf[3]);
                }
            }
        }
        __syncthreads();
        if (t + 2 <= 15)
            gemm_fill(A, W, m0, n0, sb, t & 1, (t + 2) * 64, tid);
    }
}

// Projections: half in, half out (Q pre-scaled by 0.125*log2e)
__global__ __launch_bounds__(128, 4) void proj3_kernel(
    const __half* __restrict__ xq, const __half* __restrict__ xk,
    const __half* __restrict__ xv,
    const __half* __restrict__ wq, const __half* __restrict__ wk,
    const __half* __restrict__ wv,
    __half* q, __half* k, __half* v)
{
    extern __shared__ __half gsm[];
    const __half* A; const __half* W; __half* C; float scale;
    if (blockIdx.z == 0)      { A = xq; W = wq; C = q; scale = 0.125f * 1.44269504f; }
    else if (blockIdx.z == 1) { A = xk; W = wk; C = k; scale = 1.0f; }
    else                      { A = xv; W = wv; C = v; scale = 1.0f; }
    const int m0 = blockIdx.y * 128, n0 = blockIdx.x * 64;
    const int warp = threadIdx.x >> 5, lane = threadIdx.x & 31;
    const int wm = warp >> 1, wn = warp & 1;
    const int qr = lane >> 2, qc = lane & 3;
    uint32_t sb = (uint32_t)__cvta_generic_to_shared(gsm);

    float acc[4][4][4];
#pragma unroll
    for (int mi = 0; mi < 4; mi++)
#pragma unroll
        for (int nj = 0; nj < 4; nj++)
#pragma unroll
            for (int e = 0; e < 4; e++) acc[mi][nj][e] = 0.0f;

    gemm_mainloop_raw(A, W, m0, n0, sb, acc);

#pragma unroll
    for (int mi = 0; mi < 4; mi++) {
        const size_t r0 = (size_t)(m0 + wm * 64 + mi * 16 + qr) * 1024;
#pragma unroll
        for (int nj = 0; nj < 4; nj++) {
            int col = n0 + wn * 32 + nj * 8 + qc * 2;
            *(unsigned*)&C[r0 + col] =
                pack_h2(acc[mi][nj][0] * scale, acc[mi][nj][1] * scale);
            *(unsigned*)&C[r0 + 8 * 1024 + col] =
                pack_h2(acc[mi][nj][2] * scale, acc[mi][nj][3] * scale);
        }
    }
}

// Output projection: half in, fp32 out + bias
__global__ __launch_bounds__(128, 4) void gemm_bias_kernel(
    const __half* __restrict__ A, const __half* __restrict__ W,
    float* __restrict__ C, const float* __restrict__ bias)
{
    extern __shared__ __half gsm[];
    const int m0 = blockIdx.y * 128, n0 = blockIdx.x * 64;
    const int warp = threadIdx.x >> 5, lane = threadIdx.x & 31;
    const int wm = warp >> 1, wn = warp & 1;
    const int qr = lane >> 2, qc = lane & 3;
    uint32_t sb = (uint32_t)__cvta_generic_to_shared(gsm);

    float acc[4][4][4];
#pragma unroll
    for (int mi = 0; mi < 4; mi++)
#pragma unroll
        for (int nj = 0; nj < 4; nj++)
#pragma unroll
            for (int e = 0; e < 4; e++) acc[mi][nj][e] = 0.0f;

    gemm_mainloop_raw(A, W, m0, n0, sb, acc);

#pragma unroll
    for (int mi = 0; mi < 4; mi++) {
        const size_t r0 = (size_t)(m0 + wm * 64 + mi * 16 + qr) * 1024;
#pragma unroll
        for (int nj = 0; nj < 4; nj++) {
            int col = n0 + wn * 32 + nj * 8 + qc * 2;
            float b0 = __ldg(&bias[col]), b1 = __ldg(&bias[col + 1]);
            float2 v0 = { acc[mi][nj][0] + b0, acc[mi][nj][1] + b1 };
            float2 v1 = { acc[mi][nj][2] + b0, acc[mi][nj][3] + b1 };
            *(float2*)&C[r0 + col] = v0;
            *(float2*)&C[r0 + 8 * 1024 + col] = v1;
        }
    }
}

// ---------------------------------------------------------------------------
// Flash attention v5 (unchanged from R10 best): raw mma, register P,
// chunked softmax, Q overlay, 3 CTAs/SM.
// ---------------------------------------------------------------------------
#define AST 36864
#define AOFF_V 18432
#define AOFF_QTMP 36864
#define AOFF_LR  73728
#define ATTN_SMEM 74240

__global__ __launch_bounds__(256, 3) void attn_kernel(
    const __half* __restrict__ Q, const __half* __restrict__ K,
    const __half* __restrict__ V, __half* __restrict__ CTX)
{
    extern __shared__ char smraw[];
    float* l_red = (float*)(smraw + AOFF_LR);
    uint32_t sb = (uint32_t)__cvta_generic_to_shared(smraw);

    const int tid  = threadIdx.x;
    const int warp = tid >> 5;
    const int lane = tid & 31;
    const int wm   = warp >> 1;
    const int wk2  = warp & 1;
    const int qr   = lane >> 2;
    const int qc   = lane & 3;
    const int b    = blockIdx.y >> 4;
    const int h    = blockIdx.y & 15;
    const int s0   = blockIdx.x * 64;
    const size_t base = (size_t)b * SEQ * EMBED + (size_t)h * HDIM;

#pragma unroll
    for (int i = 0; i < 2; i++) {
        int idx = tid + i * 256;
        int row = idx >> 3;
        int c8  = (idx & 7) * 8;
        cp16(sb + AOFF_QTMP + (row * ALD + c8) * 2,
             &Q[base + (size_t)(s0 + row) * 1024 + c8]);
    }
#pragma unroll
    for (int i = 0; i < 4; i++) {
        int idx = tid + i * 256;
        int row = idx >> 3;
        int c8  = (idx & 7) * 8;
        cp16(sb + (row * ALD + c8) * 2,
             &K[base + (size_t)row * 1024 + c8]);
        cp16(sb + AOFF_V + (row * ALD + c8) * 2,
             &V[base + (size_t)row * 1024 + c8]);
    }
    CP_COMMIT();
    if (tid < 64) l_red[tid] = 0.0f;

    CP_WAIT(0);
    __syncthreads();

    uint32_t qf[4][4];
#pragma unroll
    for (int kd = 0; kd < 4; kd++)
        ldsm_x4(qf[kd], ldsm_addr(sb + AOFF_QTMP, wm * 16, kd * 16, lane));
    __syncthreads();

    float oacc[8][4];
#pragma unroll
    for (int i = 0; i < 8; i++)
#pragma unroll
        for (int e = 0; e < 4; e++) oacc[i][e] = 0.0f;
    float lsum0 = 0.0f, lsum1 = 0.0f;

    for (int j = 0; j < 16; j++) {
        if (j > 0) { CP_WAIT(0); __syncthreads(); }
        if (j < 15) {
            uint32_t st = ((j + 1) & 1) ? AST : 0u;
            const size_t gb = base + (size_t)((j + 1) * 128) * 1024;
#pragma unroll
            for (int i = 0; i < 4; i++) {
                int idx = tid + i * 256;
                int row = idx >> 3;
                int c8  = (idx & 7) * 8;
                cp16(sb + st + (row * ALD + c8) * 2,
                     &K[gb + (size_t)row * 1024 + c8]);
                cp16(sb + st + AOFF_V + (row * ALD + c8) * 2,
                     &V[gb + (size_t)row * 1024 + c8]);
            }
            CP_COMMIT();
        }

        const uint32_t bK = sb + ((j & 1) ? AST : 0u);
        const uint32_t bV = bK + AOFF_V;

#pragma unroll
        for (int h2 = 0; h2 < 2; h2++) {
            const int key0 = wk2 * 64 + h2 * 32;

            float sc[4][4];
#pragma unroll
            for (int i = 0; i < 4; i++)
#pragma unroll
                for (int e = 0; e < 4; e++) sc[i][e] = 0.0f;
#pragma unroll
            for (int kd = 0; kd < 4; kd++) {
#pragma unroll
                for (int kn = 0; kn < 2; kn++) {
                    uint32_t bf[4];
                    ldsm_x4(bf, ldsm_addr(bK, key0 + kn * 16, kd * 16, lane));
                    mma16816(sc[2 * kn],     qf[kd], bf[0], bf[2]);
                    mma16816(sc[2 * kn + 1], qf[kd], bf[1], bf[3]);
                }
            }

            uint32_t pf[2][4];
#pragma unroll
            for (int t = 0; t < 2; t++) {
                float e00 = ex2(sc[2*t][0]),   e01 = ex2(sc[2*t][1]);
                float e02 = ex2(sc[2*t][2]),   e03 = ex2(sc[2*t][3]);
                float e10 = ex2(sc[2*t+1][0]), e11 = ex2(sc[2*t+1][1]);
                float e12 = ex2(sc[2*t+1][2]), e13 = ex2(sc[2*t+1][3]);
                lsum0 += e00 + e01 + e10 + e11;
                lsum1 += e02 + e03 + e12 + e13;
                pf[t][0] = pack_h2(e00, e01);
                pf[t][1] = pack_h2(e02, e03);
                pf[t][2] = pack_h2(e10, e11);
                pf[t][3] = pack_h2(e12, e13);
            }

#pragma unroll
            for (int t = 0; t < 2; t++) {
#pragma unroll
                for (int dn = 0; dn < 4; dn++) {
                    uint32_t vf[4];
                    ldsm_x4_t(vf, ldsm_addr(bV, key0 + t * 16, dn * 16, lane));
                    mma16816(oacc[2 * dn],     pf[t], vf[0], vf[1]);
                    mma16816(oacc[2 * dn + 1], pf[t], vf[2], vf[3]);
                }
            }
        }
    }

    lsum0 += __shfl_xor_sync(0xffffffffu, lsum0, 1);
    lsum0 += __shfl_xor_sync(0xffffffffu, lsum0, 2);
    lsum1 += __shfl_xor_sync(0xffffffffu, lsum1, 1);
    lsum1 += __shfl_xor_sync(0xffffffffu, lsum1, 2);
    if (qc == 0) {
        atomicAdd(&l_red[wm * 16 + qr], lsum0);
        atomicAdd(&l_red[wm * 16 + qr + 8], lsum1);
    }
    __syncthreads();

    float* Cs = (float*)smraw;
    if (wk2 == 0) {
#pragma unroll
        for (int dn = 0; dn < 8; dn++) {
            int col = dn * 8 + qc * 2;
            Cs[(wm * 16 + qr) * 68 + col]         = oacc[dn][0];
            Cs[(wm * 16 + qr) * 68 + col + 1]     = oacc[dn][1];
            Cs[(wm * 16 + qr + 8) * 68 + col]     = oacc[dn][2];
            Cs[(wm * 16 + qr + 8) * 68 + col + 1] = oacc[dn][3];
        }
    }
    __syncthreads();
    if (wk2 == 1) {
#pragma unroll
        for (int dn = 0; dn < 8; dn++) {
            int col = dn * 8 + qc * 2;
            Cs[(wm * 16 + qr) * 68 + col]         += oacc[dn][0];
            Cs[(wm * 16 + qr) * 68 + col + 1]     += oacc[dn][1];
            Cs[(wm * 16 + qr + 8) * 68 + col]     += oacc[dn][2];
            Cs[(wm * 16 + qr + 8) * 68 + col + 1] += oacc[dn][3];
        }
    }
    __syncthreads();

#pragma unroll
    for (int i = 0; i < 2; i++) {
        int idx = tid + i * 256;
        int row = idx >> 3;
        int c8  = (idx & 7) * 8;
        float rl = __frcp_rn(l_red[row]);
        float4 v0 = *(float4*)&Cs[row * 68 + c8];
        float4 v1 = *(float4*)&Cs[row * 68 + c8 + 4];
        uint4 u;
        u.x = pack_h2(v0.x * rl, v0.y * rl);
        u.y = pack_h2(v0.z * rl, v0.w * rl);
        u.z = pack_h2(v1.x * rl, v1.y * rl);
        u.w = pack_h2(v1.z * rl, v1.w * rl);
        *(uint4*)&CTX[base + (size_t)(s0 + row) * 1024 + c8] = u;
    }
}

// ---------------------------------------------------------------------------
// Launch
// ---------------------------------------------------------------------------
extern "C" void kernel_launch(void* const* d_in, const int* in_sizes, int n_in,
                              void* d_out, int out_size)
{
    const float* key   = (const float*)d_in[0];
    const float* query = (const float*)d_in[1];
    const float* value = (const float*)d_in[2];
    const float* Wq    = (const float*)d_in[3];
    const float* Wk    = (const float*)d_in[4];
    const float* Wv    = (const float*)d_in[5];
    const float* Wo    = (const float*)d_in[6];
    const float* bo    = (const float*)d_in[7];
    float* out = (float*)d_out;

    __half *hXq, *hXk, *hXv, *hWq, *hWk, *hWv, *hWo, *hQ, *hK, *hV, *hCTX;
    cudaGetSymbolAddress((void**)&hXq, g_hXq);
    cudaGetSymbolAddress((void**)&hXk, g_hXk);
    cudaGetSymbolAddress((void**)&hXv, g_hXv);
    cudaGetSymbolAddress((void**)&hWq, g_hWq);
    cudaGetSymbolAddress((void**)&hWk, g_hWk);
    cudaGetSymbolAddress((void**)&hWv, g_hWv);
    cudaGetSymbolAddress((void**)&hWo, g_hWo);
    cudaGetSymbolAddress((void**)&hQ, g_hQ);
    cudaGetSymbolAddress((void**)&hK, g_hK);
    cudaGetSymbolAddress((void**)&hV, g_hV);
    cudaGetSymbolAddress((void**)&hCTX, g_hCTX);

    const int cvt_total = 3 * X4 + 4 * W4;
    cvt_all<<<cvt_total / 512, 256>>>(query, key, value, Wq, Wk, Wv, Wo,
                                      hXq, hXk, hXv, hWq, hWk, hWv, hWo);

    cudaFuncSetAttribute(proj3_kernel,
        cudaFuncAttributeMaxDynamicSharedMemorySize, GEMM_SMEM);
    cudaFuncSetAttribute(gemm_bias_kernel,
        cudaFuncAttributeMaxDynamicSharedMemorySize, GEMM_SMEM);
    cudaFuncSetAttribute(attn_kernel,
        cudaFuncAttributeMaxDynamicSharedMemorySize, ATTN_SMEM);

    dim3 proj_grid(EMBED / 64, MTOT / 128, 3);   // (16, 32, 3)
    proj3_kernel<<<proj_grid, 128, GEMM_SMEM>>>(
        hXq, hXk, hXv, hWq, hWk, hWv, hQ, hK, hV);

    attn_kernel<<<dim3(SEQ / 64, BATCH * NHEADS), 256, ATTN_SMEM>>>(
        hQ, hK, hV, hCTX);

    gemm_bias_kernel<<<dim3(EMBED / 64, MTOT / 128), 128, GEMM_SMEM>>>(
        hCTX, hWo, out, bo);
}